// round 4
// baseline (speedup 1.0000x reference)
#include <cuda_runtime.h>
#include <cstdint>

// Fused edge-MLP, register-blocked FFMA2 version.
//   x = [e | h[src]+h[dst]]   [E,256] -> 3x (leaky o linear) -> out [E,128]
//
// CTA = 64 edges, 128 threads. Thread (fg,eg) owns features fg*4..fg*4+3 x
// edges eg*16..eg*16+15  => 64 fp32 accumulators = 32 fma.rn.f32x2 chains.
// Per k-step: 4 LDS128 (x, shared across 4 features) + 1 LDS128 (w, shared
// across 8 edge-pairs) feed 32 FFMA2  => FMA-pipe bound, not LSU bound.
// Layer-1 input streamed from gmem in 32-k chunks (small smem => 2 CTAs/SM).

#define NT     128
#define TILE_E 64
#define DD     128
#define STRX   68    // floats; 272B rows, 16B-aligned, conflict-friendly
#define STRW   132   // floats; 528B rows, 16B-aligned

__device__ __forceinline__ unsigned long long pack2(float a, float b) {
    unsigned long long r;
    asm("mov.b64 %0, {%1,%2};" : "=l"(r) : "f"(a), "f"(b));
    return r;
}
__device__ __forceinline__ void unpack2(unsigned long long v, float& a, float& b) {
    asm("mov.b64 {%0,%1}, %2;" : "=f"(a), "=f"(b) : "l"(v));
}
__device__ __forceinline__ unsigned long long fma2(unsigned long long a,
                                                   unsigned long long b,
                                                   unsigned long long c) {
    unsigned long long r;
    asm("fma.rn.f32x2 %0, %1, %2, %3;" : "=l"(r) : "l"(a), "l"(b), "l"(c));
    return r;
}
__device__ __forceinline__ float leaky(float v) { return v >= 0.0f ? v : 0.01f * v; }

// Stage W[:,c*32 .. c*32+31] -> wsh[kk][row] (transposed), coalesced LDG128.
__device__ __forceinline__ void stage_w(const float* __restrict__ W, int Kin, int c,
                                        float* wsh, int tid) {
#pragma unroll
    for (int p = 0; p < 8; ++p) {
        int i = tid + p * NT;          // 0..1023
        int row = i >> 3, seg = i & 7; // row 0..127, seg 0..7 (4 floats each)
        float4 v = *(const float4*)(W + (size_t)row * Kin + c * 32 + seg * 4);
        wsh[(seg * 4 + 0) * STRW + row] = v.x;
        wsh[(seg * 4 + 1) * STRW + row] = v.y;
        wsh[(seg * 4 + 2) * STRW + row] = v.z;
        wsh[(seg * 4 + 3) * STRW + row] = v.w;
    }
}

// Stage e chunk: xs[k][e] = e_in[base+e][c*32+k]
__device__ __forceinline__ void stage_x_e(const float* __restrict__ e_in, int base,
                                          int E, int c, float* xs, int tid) {
    int e = tid >> 1, half = tid & 1;
    int ge = base + e;
    const float* s = e_in + (size_t)ge * DD + c * 32 + half * 16;
#pragma unroll
    for (int q = 0; q < 4; ++q) {
        float4 v = make_float4(0.f, 0.f, 0.f, 0.f);
        if (ge < E) v = *(const float4*)(s + q * 4);
        int k = half * 16 + q * 4;
        xs[(k + 0) * STRX + e] = v.x;
        xs[(k + 1) * STRX + e] = v.y;
        xs[(k + 2) * STRX + e] = v.z;
        xs[(k + 3) * STRX + e] = v.w;
    }
}

// Stage h-sum chunk: xs[k][e] = h[src[e]][c*32+k] + h[dst[e]][c*32+k]
__device__ __forceinline__ void stage_x_h(const float* __restrict__ h,
                                          const int* sidx, int base, int E, int c,
                                          float* xs, int tid) {
    int e = tid >> 1, half = tid & 1;
    int ge = base + e;
    int si = sidx[e], di = sidx[TILE_E + e];
    const float* ps = h + (size_t)si * DD + c * 32 + half * 16;
    const float* pd = h + (size_t)di * DD + c * 32 + half * 16;
#pragma unroll
    for (int q = 0; q < 4; ++q) {
        float4 a = make_float4(0.f, 0.f, 0.f, 0.f);
        if (ge < E) {
            float4 va = *(const float4*)(ps + q * 4);
            float4 vb = *(const float4*)(pd + q * 4);
            a = make_float4(va.x + vb.x, va.y + vb.y, va.z + vb.z, va.w + vb.w);
        }
        int k = half * 16 + q * 4;
        xs[(k + 0) * STRX + e] = a.x;
        xs[(k + 1) * STRX + e] = a.y;
        xs[(k + 2) * STRX + e] = a.z;
        xs[(k + 3) * STRX + e] = a.w;
    }
}

// 32-k chunk of the GEMM: acc[4 feat][8 edge-pairs] += x * w
__device__ __forceinline__ void mma_chunk(const float* __restrict__ xbase,
                                          const float* __restrict__ wsh,
                                          int fg, int eg,
                                          unsigned long long acc[4][8]) {
#pragma unroll 8
    for (int kk = 0; kk < 32; ++kk) {
        float4 wv = *(const float4*)(wsh + kk * STRW + fg * 4);
        const float* xr = xbase + kk * STRX + eg * 16;
        ulonglong2 x01 = *(const ulonglong2*)(xr);
        ulonglong2 x23 = *(const ulonglong2*)(xr + 4);
        ulonglong2 x45 = *(const ulonglong2*)(xr + 8);
        ulonglong2 x67 = *(const ulonglong2*)(xr + 12);
        unsigned long long xp[8] = {x01.x, x01.y, x23.x, x23.y,
                                    x45.x, x45.y, x67.x, x67.y};
        float wf[4] = {wv.x, wv.y, wv.z, wv.w};
#pragma unroll
        for (int i = 0; i < 4; ++i) {
            unsigned long long w2 = pack2(wf[i], wf[i]);
#pragma unroll
            for (int p = 0; p < 8; ++p) acc[i][p] = fma2(xp[p], w2, acc[i][p]);
        }
    }
}

__device__ __forceinline__ void init_acc(const float* __restrict__ b, int fg,
                                         unsigned long long acc[4][8]) {
    float4 bv = *(const float4*)(b + fg * 4);
    float bf[4] = {bv.x, bv.y, bv.z, bv.w};
#pragma unroll
    for (int i = 0; i < 4; ++i) {
        unsigned long long b2 = pack2(bf[i], bf[i]);
#pragma unroll
        for (int p = 0; p < 8; ++p) acc[i][p] = b2;
    }
}

__device__ __forceinline__ void store_act_smem(unsigned long long acc[4][8],
                                               float* out_sh, int fg, int eg) {
#pragma unroll
    for (int i = 0; i < 4; ++i) {
        float* row = out_sh + (fg * 4 + i) * STRX + eg * 16;
#pragma unroll
        for (int p = 0; p < 8; ++p) {
            float a, b;
            unpack2(acc[i][p], a, b);
            *(unsigned long long*)(row + 2 * p) = pack2(leaky(a), leaky(b));
        }
    }
}

__global__ __launch_bounds__(NT, 2)
void edge_mlp_kernel(const float* __restrict__ e_in,
                     const float* __restrict__ h,
                     const int* __restrict__ src,
                     const int* __restrict__ dst,
                     const float* __restrict__ W1, const float* __restrict__ b1,
                     const float* __restrict__ W2, const float* __restrict__ b2,
                     const float* __restrict__ W3, const float* __restrict__ b3,
                     float* __restrict__ out, int E) {
    extern __shared__ float smem[];
    float* xs  = smem;                   // [32][STRX]
    float* ys  = xs + 32 * STRX;         // [128][STRX]
    float* zs  = ys + DD * STRX;         // [128][STRX]
    float* wsh = zs + DD * STRX;         // [32][STRW]
    int* sidx  = (int*)(wsh + 32 * STRW);// [2*TILE_E]

    const int tid  = threadIdx.x;
    const int base = blockIdx.x * TILE_E;
    const int fg = tid >> 2;   // feature group (4 feats)
    const int eg = tid & 3;    // edge group (16 edges)

    // Stage src/dst indices (first used at layer-1 chunk 4, after barriers).
    {
        int e = tid & (TILE_E - 1);
        int ge = base + e;
        const int* arr = (tid < TILE_E) ? src : dst;
        sidx[tid] = (ge < E) ? arr[ge] : 0;
    }

    unsigned long long acc[4][8];

    // ---- Layer 1: K=256 (e | hsum), streamed in 8 chunks ----
    init_acc(b1, fg, acc);
    for (int c = 0; c < 8; ++c) {
        __syncthreads();
        if (c < 4) stage_x_e(e_in, base, E, c, xs, tid);
        else       stage_x_h(h, sidx, base, E, c - 4, xs, tid);
        stage_w(W1, 256, c, wsh, tid);
        __syncthreads();
        mma_chunk(xs, wsh, fg, eg, acc);
    }
    store_act_smem(acc, ys, fg, eg);

    // ---- Layer 2: K=128, input ys already in smem ----
    init_acc(b2, fg, acc);
    for (int c = 0; c < 4; ++c) {
        __syncthreads();   // first iter also orders ys stores above
        stage_w(W2, 128, c, wsh, tid);
        __syncthreads();
        mma_chunk(ys + c * 32 * STRX, wsh, fg, eg, acc);
    }
    store_act_smem(acc, zs, fg, eg);

    // ---- Layer 3: K=128, input zs, output to gmem ----
    init_acc(b3, fg, acc);
    for (int c = 0; c < 4; ++c) {
        __syncthreads();
        stage_w(W3, 128, c, wsh, tid);
        __syncthreads();
        mma_chunk(zs + c * 32 * STRX, wsh, fg, eg, acc);
    }

    // Final store: per edge, float4 of this thread's 4 features (coalesced).
#pragma unroll
    for (int ee = 0; ee < 16; ++ee) {
        int p = ee >> 1, hi = ee & 1;
        float4 v;
        float a, b;
        unpack2(acc[0][p], a, b); v.x = leaky(hi ? b : a);
        unpack2(acc[1][p], a, b); v.y = leaky(hi ? b : a);
        unpack2(acc[2][p], a, b); v.z = leaky(hi ? b : a);
        unpack2(acc[3][p], a, b); v.w = leaky(hi ? b : a);
        int edge = base + eg * 16 + ee;
        if (edge < E)
            *(float4*)(out + (size_t)edge * DD + fg * 4) = v;
    }
}

extern "C" void kernel_launch(void* const* d_in, const int* in_sizes, int n_in,
                              void* d_out, int out_size) {
    const float* e_in = (const float*)d_in[0];
    const float* h    = (const float*)d_in[1];
    const int*   src  = (const int*)d_in[2];
    const int*   dst  = (const int*)d_in[3];
    const float* W1   = (const float*)d_in[4];
    const float* b1   = (const float*)d_in[5];
    const float* W2   = (const float*)d_in[6];
    const float* b2   = (const float*)d_in[7];
    const float* W3   = (const float*)d_in[8];
    const float* b3   = (const float*)d_in[9];
    float* out = (float*)d_out;

    const int E = in_sizes[0] / DD;

    const int smem_bytes =
        (32 * STRX + 2 * DD * STRX + 32 * STRW) * (int)sizeof(float)
        + 2 * TILE_E * (int)sizeof(int);

    static bool configured = false;
    if (!configured) {
        cudaFuncSetAttribute(edge_mlp_kernel,
                             cudaFuncAttributeMaxDynamicSharedMemorySize, smem_bytes);
        configured = true;
    }

    const int grid = (E + TILE_E - 1) / TILE_E;
    edge_mlp_kernel<<<grid, NT, smem_bytes>>>(e_in, h, src, dst,
                                              W1, b1, W2, b2, W3, b3, out, E);
}

// round 10
// speedup vs baseline: 6.6478x; 6.6478x over previous
#include <cuda_runtime.h>
#include <cuda_bf16.h>
#include <cstdint>

// Fused edge-MLP on HMMA (mma.sync m16n8k16 bf16, fp32 accum), split-precision:
//   x = [e | h[src]+h[dst]]  [E,256] -> 3x (leaky o linear) -> out [E,128]
// D = Ah*Wh + Al*Wh + Ah*Wl  (bf16 hi/lo split of fp32 ~ 1e-5 rel err).
//
// CTA = 128 edges, 256 threads (8 warps); warp w owns edges [16w,16w+16) x all
// 128 outputs = 16 m16n8 accum tiles. W is pre-fragmented into per-lane uint4
// {hi_r0,hi_r1,lo_r0,lo_r1} images in global, staged to smem in 64KB chunks:
// inner loop = 1 LDS.128 per 3 MMAs. Activations for layers 2/3 stay in
// registers (C m16n8 layout == A m16k8 half layout).

#define NT     256
#define TILE_M 128
#define DD     128

// W fragment image: [gk (0..31)][jtile 0..15][lane 0..31] -> uint4
//   gk 0..15 : layer1 ksteps (K=256), gk 16..23 : layer2, gk 24..31 : layer3
__device__ uint4 g_wfrag[32 * 16 * 32];   // 256 KB

__device__ __forceinline__ uint32_t pack_bf16(__nv_bfloat16 a, __nv_bfloat16 b) {
    __nv_bfloat162 t;
    t.x = a; t.y = b;               // a -> low half (first/even element)
    return *(uint32_t*)&t;
}
__device__ __forceinline__ void split_pack(float x, float y,
                                           uint32_t& hi, uint32_t& lo) {
    __nv_bfloat16 h0 = __float2bfloat16(x);
    __nv_bfloat16 h1 = __float2bfloat16(y);
    float r0 = x - __bfloat162float(h0);
    float r1 = y - __bfloat162float(h1);
    hi = pack_bf16(h0, h1);
    lo = pack_bf16(__float2bfloat16(r0), __float2bfloat16(r1));
}
__device__ __forceinline__ float leaky(float v) { return v >= 0.f ? v : 0.01f * v; }

__device__ __forceinline__ void mma_bf16(float c[4], const uint32_t a[4],
                                         uint32_t b0, uint32_t b1) {
    asm volatile(
        "mma.sync.aligned.m16n8k16.row.col.f32.bf16.bf16.f32 "
        "{%0,%1,%2,%3}, {%4,%5,%6,%7}, {%8,%9}, {%0,%1,%2,%3};"
        : "+f"(c[0]), "+f"(c[1]), "+f"(c[2]), "+f"(c[3])
        : "r"(a[0]), "r"(a[1]), "r"(a[2]), "r"(a[3]), "r"(b0), "r"(b1));
}

// ---- kernel 0: build per-lane W fragment image (one-time, tiny) ----
__global__ void build_wfrag(const float* __restrict__ W1,
                            const float* __restrict__ W2,
                            const float* __restrict__ W3) {
    int idx = blockIdx.x * blockDim.x + threadIdx.x;
    if (idx >= 32 * 16 * 32) return;
    int lane = idx & 31;
    int j    = (idx >> 5) & 15;
    int gk   = idx >> 9;
    const float* W; int Kin, kk;
    if (gk < 16)      { W = W1; Kin = 256; kk = gk; }
    else if (gk < 24) { W = W2; Kin = 128; kk = gk - 16; }
    else              { W = W3; Kin = 128; kk = gk - 24; }
    int g = lane >> 2, t = lane & 3;
    int n = 8 * j + g;
    int K0 = 16 * kk;
    const float* r = W + (size_t)n * Kin + K0;
    float w0 = r[2 * t],     w1 = r[2 * t + 1];
    float w2 = r[2 * t + 8], w3 = r[2 * t + 9];
    uint4 o;
    split_pack(w0, w1, o.x, o.z);
    split_pack(w2, w3, o.y, o.w);
    g_wfrag[idx] = o;
}

// ---- inner product step: one k16 over all 16 n-tiles, 3 split terms ----
__device__ __forceinline__ void kstep(float acc[16][4], const uint32_t ahi[4],
                                      const uint32_t alo[4], const uint4* wrow,
                                      int lane) {
#pragma unroll
    for (int j = 0; j < 16; ++j) {
        uint4 wv = wrow[j * 32 + lane];
        mma_bf16(acc[j], ahi, wv.x, wv.y);   // Ah*Wh
        mma_bf16(acc[j], alo, wv.x, wv.y);   // Al*Wh
        mma_bf16(acc[j], ahi, wv.z, wv.w);   // Ah*Wl
    }
}

__device__ __forceinline__ void bias_act(float acc[16][4], const float* sbias,
                                         int t) {
#pragma unroll
    for (int j = 0; j < 16; ++j) {
        float2 b = *(const float2*)(sbias + 8 * j + 2 * t);
        acc[j][0] = leaky(acc[j][0] + b.x);
        acc[j][1] = leaky(acc[j][1] + b.y);
        acc[j][2] = leaky(acc[j][2] + b.x);
        acc[j][3] = leaky(acc[j][3] + b.y);
    }
}

// C tiles -> next-layer A fragments (in-register; layouts match).
__device__ __forceinline__ void c_to_a(const float acc[16][4],
                                       uint32_t ahi[8][4], uint32_t alo[8][4]) {
#pragma unroll
    for (int kk = 0; kk < 8; ++kk) {
        const float* c0 = acc[2 * kk];
        const float* c1 = acc[2 * kk + 1];
        split_pack(c0[0], c0[1], ahi[kk][0], alo[kk][0]);
        split_pack(c0[2], c0[3], ahi[kk][1], alo[kk][1]);
        split_pack(c1[0], c1[1], ahi[kk][2], alo[kk][2]);
        split_pack(c1[2], c1[3], ahi[kk][3], alo[kk][3]);
    }
}

__global__ __launch_bounds__(NT, 1)
void edge_mlp_hmma(const float* __restrict__ e_in, const float* __restrict__ h,
                   const int* __restrict__ src, const int* __restrict__ dst,
                   const float* __restrict__ b1, const float* __restrict__ b2,
                   const float* __restrict__ b3, float* __restrict__ out,
                   int E) {
    extern __shared__ unsigned char smraw[];
    uint4* wbuf  = (uint4*)smraw;               // 4096 uint4 = 64 KB chunk
    float* sbias = (float*)(smraw + 65536);     // 128 floats

    const int tid  = threadIdx.x;
    const int lane = tid & 31;
    const int w    = tid >> 5;
    const int g    = lane >> 2;
    const int t    = lane & 3;

    const int base = blockIdx.x * TILE_M;
    const int e0 = base + 16 * w + g;
    const int e1 = e0 + 8;
    const bool v0 = e0 < E, v1 = e1 < E;
    const int si0 = v0 ? src[e0] : 0, di0 = v0 ? dst[e0] : 0;
    const int si1 = v1 ? src[e1] : 0, di1 = v1 ? dst[e1] : 0;

    float acc[16][4];
#pragma unroll
    for (int j = 0; j < 16; ++j)
        acc[j][0] = acc[j][1] = acc[j][2] = acc[j][3] = 0.f;

    // ---------- layer 1, chunk 0: e part (x cols 0..127) ----------
#pragma unroll
    for (int i = 0; i < 16; ++i)
        wbuf[tid + i * NT] = g_wfrag[tid + i * NT];
    if (tid < DD) sbias[tid] = b1[tid];
    __syncthreads();

#pragma unroll
    for (int kk = 0; kk < 8; ++kk) {
        const int K0 = 16 * kk;
        float2 z = make_float2(0.f, 0.f);
        float2 p0 = v0 ? *(const float2*)(e_in + (size_t)e0 * DD + K0 + 2 * t)     : z;
        float2 p1 = v1 ? *(const float2*)(e_in + (size_t)e1 * DD + K0 + 2 * t)     : z;
        float2 p2 = v0 ? *(const float2*)(e_in + (size_t)e0 * DD + K0 + 2 * t + 8) : z;
        float2 p3 = v1 ? *(const float2*)(e_in + (size_t)e1 * DD + K0 + 2 * t + 8) : z;
        uint32_t ahi[4], alo[4];
        split_pack(p0.x, p0.y, ahi[0], alo[0]);
        split_pack(p1.x, p1.y, ahi[1], alo[1]);
        split_pack(p2.x, p2.y, ahi[2], alo[2]);
        split_pack(p3.x, p3.y, ahi[3], alo[3]);
        kstep(acc, ahi, alo, wbuf + kk * 16 * 32, lane);
    }

    // ---------- layer 1, chunk 1: h-sum part (x cols 128..255) ----------
    __syncthreads();
#pragma unroll
    for (int i = 0; i < 16; ++i)
        wbuf[tid + i * NT] = g_wfrag[4096 + tid + i * NT];
    __syncthreads();

#pragma unroll
    for (int kk = 0; kk < 8; ++kk) {
        const int K0 = 16 * kk;
        float2 z = make_float2(0.f, 0.f);
        float2 p0 = z, p1 = z, p2 = z, p3 = z;
        if (v0) {
            float2 a = *(const float2*)(h + (size_t)si0 * DD + K0 + 2 * t);
            float2 b = *(const float2*)(h + (size_t)di0 * DD + K0 + 2 * t);
            p0 = make_float2(a.x + b.x, a.y + b.y);
            a = *(const float2*)(h + (size_t)si0 * DD + K0 + 2 * t + 8);
            b = *(const float2*)(h + (size_t)di0 * DD + K0 + 2 * t + 8);
            p2 = make_float2(a.x + b.x, a.y + b.y);
        }
        if (v1) {
            float2 a = *(const float2*)(h + (size_t)si1 * DD + K0 + 2 * t);
            float2 b = *(const float2*)(h + (size_t)di1 * DD + K0 + 2 * t);
            p1 = make_float2(a.x + b.x, a.y + b.y);
            a = *(const float2*)(h + (size_t)si1 * DD + K0 + 2 * t + 8);
            b = *(const float2*)(h + (size_t)di1 * DD + K0 + 2 * t + 8);
            p3 = make_float2(a.x + b.x, a.y + b.y);
        }
        uint32_t ahi[4], alo[4];
        split_pack(p0.x, p0.y, ahi[0], alo[0]);
        split_pack(p1.x, p1.y, ahi[1], alo[1]);
        split_pack(p2.x, p2.y, ahi[2], alo[2]);
        split_pack(p3.x, p3.y, ahi[3], alo[3]);
        kstep(acc, ahi, alo, wbuf + kk * 16 * 32, lane);
    }

    // ---------- epilogue 1 -> register A fragments ----------
    uint32_t ahi[8][4], alo[8][4];
    bias_act(acc, sbias, t);
    c_to_a(acc, ahi, alo);
#pragma unroll
    for (int j = 0; j < 16; ++j)
        acc[j][0] = acc[j][1] = acc[j][2] = acc[j][3] = 0.f;

    // ---------- layer 2 ----------
    __syncthreads();
#pragma unroll
    for (int i = 0; i < 16; ++i)
        wbuf[tid + i * NT] = g_wfrag[8192 + tid + i * NT];
    if (tid < DD) sbias[tid] = b2[tid];
    __syncthreads();
#pragma unroll
    for (int kk = 0; kk < 8; ++kk)
        kstep(acc, ahi[kk], alo[kk], wbuf + kk * 16 * 32, lane);

    bias_act(acc, sbias, t);
    c_to_a(acc, ahi, alo);
#pragma unroll
    for (int j = 0; j < 16; ++j)
        acc[j][0] = acc[j][1] = acc[j][2] = acc[j][3] = 0.f;

    // ---------- layer 3 ----------
    __syncthreads();
#pragma unroll
    for (int i = 0; i < 16; ++i)
        wbuf[tid + i * NT] = g_wfrag[12288 + tid + i * NT];
    if (tid < DD) sbias[tid] = b3[tid];
    __syncthreads();
#pragma unroll
    for (int kk = 0; kk < 8; ++kk)
        kstep(acc, ahi[kk], alo[kk], wbuf + kk * 16 * 32, lane);

    // ---------- final epilogue: bias + leaky + coalesced float2 stores ----------
#pragma unroll
    for (int j = 0; j < 16; ++j) {
        float2 b = *(const float2*)(sbias + 8 * j + 2 * t);
        float c0 = leaky(acc[j][0] + b.x);
        float c1 = leaky(acc[j][1] + b.y);
        float c2 = leaky(acc[j][2] + b.x);
        float c3 = leaky(acc[j][3] + b.y);
        if (v0) *(float2*)(out + (size_t)e0 * DD + 8 * j + 2 * t) = make_float2(c0, c1);
        if (v1) *(float2*)(out + (size_t)e1 * DD + 8 * j + 2 * t) = make_float2(c2, c3);
    }
}

extern "C" void kernel_launch(void* const* d_in, const int* in_sizes, int n_in,
                              void* d_out, int out_size) {
    const float* e_in = (const float*)d_in[0];
    const float* h    = (const float*)d_in[1];
    const int*   src  = (const int*)d_in[2];
    const int*   dst  = (const int*)d_in[3];
    const float* W1   = (const float*)d_in[4];
    const float* b1   = (const float*)d_in[5];
    const float* W2   = (const float*)d_in[6];
    const float* b2   = (const float*)d_in[7];
    const float* W3   = (const float*)d_in[8];
    const float* b3   = (const float*)d_in[9];
    float* out = (float*)d_out;

    const int E = in_sizes[0] / DD;
    const int smem_dyn = 65536 + DD * (int)sizeof(float);

    cudaFuncSetAttribute(edge_mlp_hmma,
                         cudaFuncAttributeMaxDynamicSharedMemorySize, smem_dyn);

    build_wfrag<<<(32 * 16 * 32 + 255) / 256, 256>>>(W1, W2, W3);
    edge_mlp_hmma<<<(E + TILE_M - 1) / TILE_M, NT, smem_dyn>>>(
        e_in, h, src, dst, b1, b2, b3, out, E);
}

// round 12
// speedup vs baseline: 9.4497x; 1.4215x over previous
#include <cuda_runtime.h>
#include <cuda_fp16.h>
#include <cstdint>

// Fused edge-MLP on HMMA (mma.sync m16n8k16 fp16, fp32 accum), 2-term split:
//   x = [e | h[src]+h[dst]]  [E,256] -> 3x (leaky o linear) -> out [E,128]
// D = Ah*W + Al*W   (A split fp16 hi/lo ~22 mantissa bits; W single fp16).
// Estimated norm rel err ~5e-4 (<1e-3 threshold).
//
// CTA = 128 edges, 256 threads (8 warps); warp w owns edges [16w,16w+16) x all
// 128 outputs = 16 m16n8 accum tiles. W pre-fragmented to per-lane uint2
// fp16x2 pairs in global, staged to smem: inner loop = 1 LDS.64 per 2 MMAs.
// Activations for layers 2/3 stay in registers (C m16n8 == A m16k8 halves).

#define NT     256
#define TILE_M 128
#define DD     128

// W fragment image: [gk (0..31)][jtile 0..15][lane 0..31] -> uint2 {b0,b1}
//   gk 0..15 : layer1 ksteps (K=256), gk 16..23 : layer2, gk 24..31 : layer3
__device__ __align__(16) uint2 g_wfrag[32 * 16 * 32];   // 128 KB

__device__ __forceinline__ uint32_t pack_h2(__half a, __half b) {
    __half2 t;
    t.x = a; t.y = b;
    return *(uint32_t*)&t;
}
__device__ __forceinline__ void split_pack(float x, float y,
                                           uint32_t& hi, uint32_t& lo) {
    __half h0 = __float2half_rn(x);
    __half h1 = __float2half_rn(y);
    float r0 = x - __half2float(h0);
    float r1 = y - __half2float(h1);
    hi = pack_h2(h0, h1);
    lo = pack_h2(__float2half_rn(r0), __float2half_rn(r1));
}
__device__ __forceinline__ float leaky(float v) { return v >= 0.f ? v : 0.01f * v; }

__device__ __forceinline__ void mma_f16(float c[4], const uint32_t a[4],
                                        uint32_t b0, uint32_t b1) {
    asm volatile(
        "mma.sync.aligned.m16n8k16.row.col.f32.f16.f16.f32 "
        "{%0,%1,%2,%3}, {%4,%5,%6,%7}, {%8,%9}, {%0,%1,%2,%3};"
        : "+f"(c[0]), "+f"(c[1]), "+f"(c[2]), "+f"(c[3])
        : "r"(a[0]), "r"(a[1]), "r"(a[2]), "r"(a[3]), "r"(b0), "r"(b1));
}

// ---- kernel 0: build per-lane W fragment image (one-time, tiny) ----
__global__ void build_wfrag(const float* __restrict__ W1,
                            const float* __restrict__ W2,
                            const float* __restrict__ W3) {
    int idx = blockIdx.x * blockDim.x + threadIdx.x;
    if (idx >= 32 * 16 * 32) return;
    int lane = idx & 31;
    int j    = (idx >> 5) & 15;
    int gk   = idx >> 9;
    const float* W; int Kin, kk;
    if (gk < 16)      { W = W1; Kin = 256; kk = gk; }
    else if (gk < 24) { W = W2; Kin = 128; kk = gk - 16; }
    else              { W = W3; Kin = 128; kk = gk - 24; }
    int g = lane >> 2, t = lane & 3;
    int n = 8 * j + g;
    int K0 = 16 * kk;
    const float* r = W + (size_t)n * Kin + K0;
    uint2 o;
    o.x = pack_h2(__float2half_rn(r[2 * t]),     __float2half_rn(r[2 * t + 1]));
    o.y = pack_h2(__float2half_rn(r[2 * t + 8]), __float2half_rn(r[2 * t + 9]));
    g_wfrag[idx] = o;
}

// ---- inner product step: one k16 over all 16 n-tiles, 2 split terms ----
__device__ __forceinline__ void kstep(float acc[16][4], const uint32_t ahi[4],
                                      const uint32_t alo[4], const uint2* wrow,
                                      int lane) {
#pragma unroll
    for (int j = 0; j < 16; ++j) {
        uint2 wv = wrow[j * 32 + lane];
        mma_f16(acc[j], ahi, wv.x, wv.y);   // Ah*W
        mma_f16(acc[j], alo, wv.x, wv.y);   // Al*W
    }
}

__device__ __forceinline__ void bias_act(float acc[16][4], const float* sbias,
                                         int t) {
#pragma unroll
    for (int j = 0; j < 16; ++j) {
        float2 b = *(const float2*)(sbias + 8 * j + 2 * t);
        acc[j][0] = leaky(acc[j][0] + b.x);
        acc[j][1] = leaky(acc[j][1] + b.y);
        acc[j][2] = leaky(acc[j][2] + b.x);
        acc[j][3] = leaky(acc[j][3] + b.y);
    }
}

// C tiles -> next-layer A fragments (in-register; layouts match).
__device__ __forceinline__ void c_to_a(const float acc[16][4],
                                       uint32_t ahi[8][4], uint32_t alo[8][4]) {
#pragma unroll
    for (int kk = 0; kk < 8; ++kk) {
        const float* c0 = acc[2 * kk];
        const float* c1 = acc[2 * kk + 1];
        split_pack(c0[0], c0[1], ahi[kk][0], alo[kk][0]);
        split_pack(c0[2], c0[3], ahi[kk][1], alo[kk][1]);
        split_pack(c1[0], c1[1], ahi[kk][2], alo[kk][2]);
        split_pack(c1[2], c1[3], ahi[kk][3], alo[kk][3]);
    }
}

__global__ __launch_bounds__(NT, 1)
void edge_mlp_hmma(const float* __restrict__ e_in, const float* __restrict__ h,
                   const int* __restrict__ src, const int* __restrict__ dst,
                   const float* __restrict__ b1, const float* __restrict__ b2,
                   const float* __restrict__ b3, float* __restrict__ out,
                   int E) {
    extern __shared__ unsigned char smraw[];
    uint2* wbuf  = (uint2*)smraw;               // up to 8192 uint2 = 64 KB
    float* sbias = (float*)(smraw + 65536);     // 128 floats

    const int tid  = threadIdx.x;
    const int lane = tid & 31;
    const int w    = tid >> 5;
    const int g    = lane >> 2;
    const int t    = lane & 3;

    const int base = blockIdx.x * TILE_M;
    const int e0 = base + 16 * w + g;
    const int e1 = e0 + 8;
    const bool v0 = e0 < E, v1 = e1 < E;
    const int si0 = v0 ? src[e0] : 0, di0 = v0 ? dst[e0] : 0;
    const int si1 = v1 ? src[e1] : 0, di1 = v1 ? dst[e1] : 0;

    float acc[16][4];
#pragma unroll
    for (int j = 0; j < 16; ++j)
        acc[j][0] = acc[j][1] = acc[j][2] = acc[j][3] = 0.f;

    // ---------- layer 1: preload all 16 ksteps of W1 frags (64 KB) ----------
    {
        const uint4* s = (const uint4*)g_wfrag;
        uint4* d = (uint4*)wbuf;
#pragma unroll
        for (int i = 0; i < 16; ++i) d[tid + i * NT] = s[tid + i * NT];
    }
    if (tid < DD) sbias[tid] = b1[tid];
    __syncthreads();

    // chunk 0: e part (x cols 0..127)
#pragma unroll
    for (int kk = 0; kk < 8; ++kk) {
        const int K0 = 16 * kk;
        float2 z = make_float2(0.f, 0.f);
        float2 p0 = v0 ? *(const float2*)(e_in + (size_t)e0 * DD + K0 + 2 * t)     : z;
        float2 p1 = v1 ? *(const float2*)(e_in + (size_t)e1 * DD + K0 + 2 * t)     : z;
        float2 p2 = v0 ? *(const float2*)(e_in + (size_t)e0 * DD + K0 + 2 * t + 8) : z;
        float2 p3 = v1 ? *(const float2*)(e_in + (size_t)e1 * DD + K0 + 2 * t + 8) : z;
        uint32_t ahi[4], alo[4];
        split_pack(p0.x, p0.y, ahi[0], alo[0]);
        split_pack(p1.x, p1.y, ahi[1], alo[1]);
        split_pack(p2.x, p2.y, ahi[2], alo[2]);
        split_pack(p3.x, p3.y, ahi[3], alo[3]);
        kstep(acc, ahi, alo, wbuf + kk * 16 * 32, lane);
    }

    // chunk 1: h-sum part (x cols 128..255)
#pragma unroll
    for (int kk = 0; kk < 8; ++kk) {
        const int K0 = 16 * kk;
        float2 z = make_float2(0.f, 0.f);
        float2 p0 = z, p1 = z, p2 = z, p3 = z;
        if (v0) {
            float2 a = *(const float2*)(h + (size_t)si0 * DD + K0 + 2 * t);
            float2 b = *(const float2*)(h + (size_t)di0 * DD + K0 + 2 * t);
            p0 = make_float2(a.x + b.x, a.y + b.y);
            a = *(const float2*)(h + (size_t)si0 * DD + K0 + 2 * t + 8);
            b = *(const float2*)(h + (size_t)di0 * DD + K0 + 2 * t + 8);
            p2 = make_float2(a.x + b.x, a.y + b.y);
        }
        if (v1) {
            float2 a = *(const float2*)(h + (size_t)si1 * DD + K0 + 2 * t);
            float2 b = *(const float2*)(h + (size_t)di1 * DD + K0 + 2 * t);
            p1 = make_float2(a.x + b.x, a.y + b.y);
            a = *(const float2*)(h + (size_t)si1 * DD + K0 + 2 * t + 8);
            b = *(const float2*)(h + (size_t)di1 * DD + K0 + 2 * t + 8);
            p3 = make_float2(a.x + b.x, a.y + b.y);
        }
        uint32_t ahi[4], alo[4];
        split_pack(p0.x, p0.y, ahi[0], alo[0]);
        split_pack(p1.x, p1.y, ahi[1], alo[1]);
        split_pack(p2.x, p2.y, ahi[2], alo[2]);
        split_pack(p3.x, p3.y, ahi[3], alo[3]);
        kstep(acc, ahi, alo, wbuf + (8 + kk) * 16 * 32, lane);
    }

    // ---------- epilogue 1 -> register A fragments ----------
    uint32_t ahi[8][4], alo[8][4];
    bias_act(acc, sbias, t);
    c_to_a(acc, ahi, alo);
#pragma unroll
    for (int j = 0; j < 16; ++j)
        acc[j][0] = acc[j][1] = acc[j][2] = acc[j][3] = 0.f;

    // ---------- layer 2 ----------
    __syncthreads();
    {
        const uint4* s = (const uint4*)(g_wfrag + 16 * 16 * 32);
        uint4* d = (uint4*)wbuf;
#pragma unroll
        for (int i = 0; i < 8; ++i) d[tid + i * NT] = s[tid + i * NT];
    }
    if (tid < DD) sbias[tid] = b2[tid];
    __syncthreads();
#pragma unroll
    for (int kk = 0; kk < 8; ++kk)
        kstep(acc, ahi[kk], alo[kk], wbuf + kk * 16 * 32, lane);

    bias_act(acc, sbias, t);
    c_to_a(acc, ahi, alo);
#pragma unroll
    for (int j = 0; j < 16; ++j)
        acc[j][0] = acc[j][1] = acc[j][2] = acc[j][3] = 0.f;

    // ---------- layer 3 ----------
    __syncthreads();
    {
        const uint4* s = (const uint4*)(g_wfrag + 24 * 16 * 32);
        uint4* d = (uint4*)wbuf;
#pragma unroll
        for (int i = 0; i < 8; ++i) d[tid + i * NT] = s[tid + i * NT];
    }
    if (tid < DD) sbias[tid] = b3[tid];
    __syncthreads();
#pragma unroll
    for (int kk = 0; kk < 8; ++kk)
        kstep(acc, ahi[kk], alo[kk], wbuf + kk * 16 * 32, lane);

    // ---------- final epilogue: bias + leaky + coalesced float2 stores ----------
#pragma unroll
    for (int j = 0; j < 16; ++j) {
        float2 b = *(const float2*)(sbias + 8 * j + 2 * t);
        float c0 = leaky(acc[j][0] + b.x);
        float c1 = leaky(acc[j][1] + b.y);
        float c2 = leaky(acc[j][2] + b.x);
        float c3 = leaky(acc[j][3] + b.y);
        if (v0) *(float2*)(out + (size_t)e0 * DD + 8 * j + 2 * t) = make_float2(c0, c1);
        if (v1) *(float2*)(out + (size_t)e1 * DD + 8 * j + 2 * t) = make_float2(c2, c3);
    }
}

extern "C" void kernel_launch(void* const* d_in, const int* in_sizes, int n_in,
                              void* d_out, int out_size) {
    const float* e_in = (const float*)d_in[0];
    const float* h    = (const float*)d_in[1];
    const int*   src  = (const int*)d_in[2];
    const int*   dst  = (const int*)d_in[3];
    const float* W1   = (const float*)d_in[4];
    const float* b1   = (const float*)d_in[5];
    const float* W2   = (const float*)d_in[6];
    const float* b2   = (const float*)d_in[7];
    const float* W3   = (const float*)d_in[8];
    const float* b3   = (const float*)d_in[9];
    float* out = (float*)d_out;

    const int E = in_sizes[0] / DD;
    const int smem_dyn = 65536 + DD * (int)sizeof(float);

    cudaFuncSetAttribute(edge_mlp_hmma,
                         cudaFuncAttributeMaxDynamicSharedMemorySize, smem_dyn);

    build_wfrag<<<(32 * 16 * 32 + 255) / 256, 256>>>(W1, W2, W3);
    edge_mlp_hmma<<<(E + TILE_M - 1) / TILE_M, NT, smem_dyn>>>(
        e_in, h, src, dst, b1, b2, b3, out, E);
}

// round 13
// speedup vs baseline: 9.8953x; 1.0472x over previous
#include <cuda_runtime.h>
#include <cuda_fp16.h>
#include <cstdint>

// Fused edge-MLP on HMMA (mma.sync m16n8k16 fp16, fp32 accum), 2-term split:
//   x = [e | h[src]+h[dst]]  [E,256] -> 3x (leaky o linear) -> out [E,128]
// D = Ah*W + Al*W   (A split fp16 hi/lo; W single fp16; rel err ~3e-4).
//
// CTA = 256 threads (8 warps) processes 4 tiles of 128 edges. ALL weight
// fragments (128 KB) staged to smem ONCE; the 4-tile loop has no barriers, so
// warps pipeline independently (gather latency of one warp hides under other
// warps' MMA streams). W image pre-paired so inner loop = 1 LDS.128 per 4 MMAs.
// Activations stay in registers across layers (C m16n8 == A m16k8 halves).

#define NT     256
#define TILE_M 128
#define DD     128
#define TILES_PER_CTA 4

// Paired W fragment image: [gk (0..31)][jp (0..7)][lane (0..31)] -> uint4
//   uint4 = {b0(j=2jp), b1(j=2jp), b0(j=2jp+1), b1(j=2jp+1)}  (fp16x2 words)
//   gk 0..15 : layer1 ksteps (K=256), gk 16..23 : layer2, gk 24..31 : layer3
__device__ __align__(16) uint4 g_wfrag4[32 * 8 * 32];   // 128 KB

__device__ __forceinline__ uint32_t pack_h2(__half a, __half b) {
    __half2 t;
    t.x = a; t.y = b;
    return *(uint32_t*)&t;
}
__device__ __forceinline__ void split_pack(float x, float y,
                                           uint32_t& hi, uint32_t& lo) {
    __half h0 = __float2half_rn(x);
    __half h1 = __float2half_rn(y);
    float r0 = x - __half2float(h0);
    float r1 = y - __half2float(h1);
    hi = pack_h2(h0, h1);
    lo = pack_h2(__float2half_rn(r0), __float2half_rn(r1));
}
__device__ __forceinline__ float leaky(float v) { return v >= 0.f ? v : 0.01f * v; }

__device__ __forceinline__ void mma_f16(float c[4], const uint32_t a[4],
                                        uint32_t b0, uint32_t b1) {
    asm volatile(
        "mma.sync.aligned.m16n8k16.row.col.f32.f16.f16.f32 "
        "{%0,%1,%2,%3}, {%4,%5,%6,%7}, {%8,%9}, {%0,%1,%2,%3};"
        : "+f"(c[0]), "+f"(c[1]), "+f"(c[2]), "+f"(c[3])
        : "r"(a[0]), "r"(a[1]), "r"(a[2]), "r"(a[3]), "r"(b0), "r"(b1));
}

// ---- kernel 0: build paired per-lane W fragment image (one-time, tiny) ----
__global__ void build_wfrag(const float* __restrict__ W1,
                            const float* __restrict__ W2,
                            const float* __restrict__ W3) {
    int idx = blockIdx.x * blockDim.x + threadIdx.x;
    if (idx >= 32 * 16 * 32) return;
    int lane = idx & 31;
    int j    = (idx >> 5) & 15;
    int gk   = idx >> 9;
    const float* W; int Kin, kk;
    if (gk < 16)      { W = W1; Kin = 256; kk = gk; }
    else if (gk < 24) { W = W2; Kin = 128; kk = gk - 16; }
    else              { W = W3; Kin = 128; kk = gk - 24; }
    int g = lane >> 2, t = lane & 3;
    int n = 8 * j + g;
    int K0 = 16 * kk;
    const float* r = W + (size_t)n * Kin + K0;
    uint2 o;
    o.x = pack_h2(__float2half_rn(r[2 * t]),     __float2half_rn(r[2 * t + 1]));
    o.y = pack_h2(__float2half_rn(r[2 * t + 8]), __float2half_rn(r[2 * t + 9]));
    // paired layout: uint4 slot = (gk*8 + j/2)*32 + lane; half = j&1
    uint2* dst = (uint2*)g_wfrag4;
    dst[(((size_t)gk * 8 + (j >> 1)) * 32 + lane) * 2 + (j & 1)] = o;
}

// ---- inner product step: one k16 over 16 n-tiles, 2 split terms ----
__device__ __forceinline__ void kstep(float acc[16][4], const uint32_t ahi[4],
                                      const uint32_t alo[4], const uint4* w4,
                                      int lane) {
#pragma unroll
    for (int jp = 0; jp < 8; ++jp) {
        uint4 wv = w4[jp * 32 + lane];
        mma_f16(acc[2 * jp],     ahi, wv.x, wv.y);
        mma_f16(acc[2 * jp],     alo, wv.x, wv.y);
        mma_f16(acc[2 * jp + 1], ahi, wv.z, wv.w);
        mma_f16(acc[2 * jp + 1], alo, wv.z, wv.w);
    }
}

__device__ __forceinline__ void bias_act(float acc[16][4], const float* sbias,
                                         int t) {
#pragma unroll
    for (int j = 0; j < 16; ++j) {
        float2 b = *(const float2*)(sbias + 8 * j + 2 * t);
        acc[j][0] = leaky(acc[j][0] + b.x);
        acc[j][1] = leaky(acc[j][1] + b.y);
        acc[j][2] = leaky(acc[j][2] + b.x);
        acc[j][3] = leaky(acc[j][3] + b.y);
    }
}

// C tiles -> next-layer A fragments (in-register; layouts match).
__device__ __forceinline__ void c_to_a(const float acc[16][4],
                                       uint32_t ahi[8][4], uint32_t alo[8][4]) {
#pragma unroll
    for (int kk = 0; kk < 8; ++kk) {
        const float* c0 = acc[2 * kk];
        const float* c1 = acc[2 * kk + 1];
        split_pack(c0[0], c0[1], ahi[kk][0], alo[kk][0]);
        split_pack(c0[2], c0[3], ahi[kk][1], alo[kk][1]);
        split_pack(c1[0], c1[1], ahi[kk][2], alo[kk][2]);
        split_pack(c1[2], c1[3], ahi[kk][3], alo[kk][3]);
    }
}

__global__ __launch_bounds__(NT, 1)
void edge_mlp_hmma(const float* __restrict__ e_in, const float* __restrict__ h,
                   const int* __restrict__ src, const int* __restrict__ dst,
                   const float* __restrict__ b1, const float* __restrict__ b2,
                   const float* __restrict__ b3, float* __restrict__ out,
                   int E) {
    extern __shared__ unsigned char smraw[];
    uint4* wsm   = (uint4*)smraw;                 // 8192 uint4 = 128 KB
    float* sbias = (float*)(smraw + 131072);      // 3 x 128 floats

    const int tid  = threadIdx.x;
    const int lane = tid & 31;
    const int w    = tid >> 5;
    const int g    = lane >> 2;
    const int t    = lane & 3;

    // ---- stage ALL weight fragments + biases once ----
#pragma unroll
    for (int i = 0; i < 32; ++i) wsm[tid + i * NT] = g_wfrag4[tid + i * NT];
    if (tid < DD) {
        sbias[tid]           = b1[tid];
        sbias[DD + tid]      = b2[tid];
        sbias[2 * DD + tid]  = b3[tid];
    }
    __syncthreads();
    // No barriers below: each warp runs the whole tile pipeline independently.

    for (int tile = 0; tile < TILES_PER_CTA; ++tile) {
        const int base = (blockIdx.x * TILES_PER_CTA + tile) * TILE_M;
        if (base >= E) break;
        const int e0 = base + 16 * w + g;
        const int e1 = e0 + 8;
        const bool v0 = e0 < E, v1 = e1 < E;
        const int si0 = v0 ? src[e0] : 0, di0 = v0 ? dst[e0] : 0;
        const int si1 = v1 ? src[e1] : 0, di1 = v1 ? dst[e1] : 0;

        float acc[16][4];
#pragma unroll
        for (int j = 0; j < 16; ++j)
            acc[j][0] = acc[j][1] = acc[j][2] = acc[j][3] = 0.f;

        // ---------- layer 1, chunk 0: e part (x cols 0..127) ----------
#pragma unroll
        for (int kk = 0; kk < 8; ++kk) {
            const int K0 = 16 * kk;
            float2 z = make_float2(0.f, 0.f);
            float2 p0 = v0 ? *(const float2*)(e_in + (size_t)e0 * DD + K0 + 2 * t)     : z;
            float2 p1 = v1 ? *(const float2*)(e_in + (size_t)e1 * DD + K0 + 2 * t)     : z;
            float2 p2 = v0 ? *(const float2*)(e_in + (size_t)e0 * DD + K0 + 2 * t + 8) : z;
            float2 p3 = v1 ? *(const float2*)(e_in + (size_t)e1 * DD + K0 + 2 * t + 8) : z;
            uint32_t fhi[4], flo[4];
            split_pack(p0.x, p0.y, fhi[0], flo[0]);
            split_pack(p1.x, p1.y, fhi[1], flo[1]);
            split_pack(p2.x, p2.y, fhi[2], flo[2]);
            split_pack(p3.x, p3.y, fhi[3], flo[3]);
            kstep(acc, fhi, flo, wsm + kk * 8 * 32, lane);
        }

        // ---------- layer 1, chunk 1: h-sum part (x cols 128..255) ----------
#pragma unroll
        for (int kk = 0; kk < 8; ++kk) {
            const int K0 = 16 * kk;
            float2 z = make_float2(0.f, 0.f);
            float2 p0 = z, p1 = z, p2 = z, p3 = z;
            if (v0) {
                float2 a = *(const float2*)(h + (size_t)si0 * DD + K0 + 2 * t);
                float2 b = *(const float2*)(h + (size_t)di0 * DD + K0 + 2 * t);
                p0 = make_float2(a.x + b.x, a.y + b.y);
                a = *(const float2*)(h + (size_t)si0 * DD + K0 + 2 * t + 8);
                b = *(const float2*)(h + (size_t)di0 * DD + K0 + 2 * t + 8);
                p2 = make_float2(a.x + b.x, a.y + b.y);
            }
            if (v1) {
                float2 a = *(const float2*)(h + (size_t)si1 * DD + K0 + 2 * t);
                float2 b = *(const float2*)(h + (size_t)di1 * DD + K0 + 2 * t);
                p1 = make_float2(a.x + b.x, a.y + b.y);
                a = *(const float2*)(h + (size_t)si1 * DD + K0 + 2 * t + 8);
                b = *(const float2*)(h + (size_t)di1 * DD + K0 + 2 * t + 8);
                p3 = make_float2(a.x + b.x, a.y + b.y);
            }
            uint32_t fhi[4], flo[4];
            split_pack(p0.x, p0.y, fhi[0], flo[0]);
            split_pack(p1.x, p1.y, fhi[1], flo[1]);
            split_pack(p2.x, p2.y, fhi[2], flo[2]);
            split_pack(p3.x, p3.y, fhi[3], flo[3]);
            kstep(acc, fhi, flo, wsm + (8 + kk) * 8 * 32, lane);
        }

        // ---------- epilogue 1 -> register A fragments ----------
        uint32_t ahi[8][4], alo[8][4];
        bias_act(acc, sbias, t);
        c_to_a(acc, ahi, alo);
#pragma unroll
        for (int j = 0; j < 16; ++j)
            acc[j][0] = acc[j][1] = acc[j][2] = acc[j][3] = 0.f;

        // ---------- layer 2 (frags at uint4 offset 4096) ----------
#pragma unroll
        for (int kk = 0; kk < 8; ++kk)
            kstep(acc, ahi[kk], alo[kk], wsm + 4096 + kk * 8 * 32, lane);

        bias_act(acc, sbias + DD, t);
        c_to_a(acc, ahi, alo);
#pragma unroll
        for (int j = 0; j < 16; ++j)
            acc[j][0] = acc[j][1] = acc[j][2] = acc[j][3] = 0.f;

        // ---------- layer 3 (frags at uint4 offset 6144) ----------
#pragma unroll
        for (int kk = 0; kk < 8; ++kk)
            kstep(acc, ahi[kk], alo[kk], wsm + 6144 + kk * 8 * 32, lane);

        // ---------- final epilogue: bias + leaky + coalesced float2 stores ----
        const float* sb3 = sbias + 2 * DD;
#pragma unroll
        for (int j = 0; j < 16; ++j) {
            float2 b = *(const float2*)(sb3 + 8 * j + 2 * t);
            float c0 = leaky(acc[j][0] + b.x);
            float c1 = leaky(acc[j][1] + b.y);
            float c2 = leaky(acc[j][2] + b.x);
            float c3 = leaky(acc[j][3] + b.y);
            if (v0) *(float2*)(out + (size_t)e0 * DD + 8 * j + 2 * t) = make_float2(c0, c1);
            if (v1) *(float2*)(out + (size_t)e1 * DD + 8 * j + 2 * t) = make_float2(c2, c3);
        }
    }
}

extern "C" void kernel_launch(void* const* d_in, const int* in_sizes, int n_in,
                              void* d_out, int out_size) {
    const float* e_in = (const float*)d_in[0];
    const float* h    = (const float*)d_in[1];
    const int*   src  = (const int*)d_in[2];
    const int*   dst  = (const int*)d_in[3];
    const float* W1   = (const float*)d_in[4];
    const float* b1   = (const float*)d_in[5];
    const float* W2   = (const float*)d_in[6];
    const float* b2   = (const float*)d_in[7];
    const float* W3   = (const float*)d_in[8];
    const float* b3   = (const float*)d_in[9];
    float* out = (float*)d_out;

    const int E = in_sizes[0] / DD;
    const int smem_dyn = 131072 + 3 * DD * (int)sizeof(float);

    cudaFuncSetAttribute(edge_mlp_hmma,
                         cudaFuncAttributeMaxDynamicSharedMemorySize, smem_dyn);

    build_wfrag<<<(32 * 16 * 32 + 255) / 256, 256>>>(W1, W2, W3);

    const int edges_per_cta = TILE_M * TILES_PER_CTA;
    const int grid = (E + edges_per_cta - 1) / edges_per_cta;
    edge_mlp_hmma<<<grid, NT, smem_dyn>>>(e_in, h, src, dst, b1, b2, b3, out, E);
}